// round 7
// baseline (speedup 1.0000x reference)
#include <cuda_runtime.h>

#define D 64
#define S 64
#define L 64
#define W 300
#define H 300
#define NROWS (D*S)          // 4096
#define NEGV (-9999999.0f)

// ---------------- device scratch (no allocation allowed) ----------------
__device__ float g_enc[NROWS * H];
__device__ float g_P  [NROWS * H];
__device__ float g_C  [NROWS * H];
__device__ float g_Y2 [NROWS * H];
__device__ float g_G  [NROWS * H];
__device__ float g_rs [NROWS];
__device__ float g_fin[D * H];
__device__ float g_v2 [H];

__device__ __forceinline__ float lrelu_f(float x) { return x > 0.f ? x : 0.01f * x; }

__device__ __forceinline__ unsigned f2tf32(float f) {
    unsigned u;
    asm("cvt.rna.tf32.f32 %0, %1;" : "=r"(u) : "f"(f));
    return u;
}
__device__ __forceinline__ uint4 cvt4(float4 v) {
    return make_uint4(f2tf32(v.x), f2tf32(v.y), f2tf32(v.z), f2tf32(v.w));
}

__device__ __forceinline__ void mma8(float* c, const unsigned* a, const unsigned* b) {
    asm volatile(
        "mma.sync.aligned.m16n8k8.row.col.f32.tf32.tf32.f32 "
        "{%0,%1,%2,%3}, {%4,%5,%6,%7}, {%8,%9}, {%0,%1,%2,%3};"
        : "+f"(c[0]), "+f"(c[1]), "+f"(c[2]), "+f"(c[3])
        : "r"(a[0]), "r"(a[1]), "r"(a[2]), "r"(a[3]), "r"(b[0]), "r"(b[1]));
}

#define BM 128
#define BN 64
#define BK 16
#define BKP 20

// =====================================================================
// TF32 GEMM (R5-proven version): Out[M,N] = act(A[M,K] @ B[N,K]^T + b)
// Single-buffer smem, two syncs per K-step. z selects (B,bias,Out,ldb).
// =====================================================================
template<bool GATHER>
__global__ __launch_bounds__(256)
void gemm_tf32_kernel(
    const float* __restrict__ Abase, const int* __restrict__ idx, int idxStride,
    const float* __restrict__ B0, const float* __restrict__ bias0, float* __restrict__ Out0,
    const float* __restrict__ B1, const float* __restrict__ bias1, float* __restrict__ Out1,
    const float* __restrict__ B2, const float* __restrict__ bias2, float* __restrict__ Out2,
    int N, int K, int ldb0, int ldb1, int ldb2)
{
    const float* Bw   = B0;
    const float* bias = bias0;
    float*       Out  = Out0;
    int          ldb  = ldb0;
    if (blockIdx.z == 1) { Bw = B1; bias = bias1; Out = Out1; ldb = ldb1; }
    if (blockIdx.z == 2) { Bw = B2; bias = bias2; Out = Out2; ldb = ldb2; }
    const bool act = (bias != nullptr);

    __shared__ __align__(16) unsigned As[BM][BKP];
    __shared__ __align__(16) unsigned Bs[BN][BKP];

    const int tid  = threadIdx.x;
    const int lane = tid & 31;
    const int wid  = tid >> 5;
    const int wm   = wid >> 1;
    const int wn   = wid & 1;
    const int m0   = blockIdx.y * BM;
    const int n0   = blockIdx.x * BN;

    const int am0 = tid >> 2;
    const int ac  = (tid & 3) * 4;
    long aoff0, aoff1;
    if (GATHER) {
        aoff0 = (long)idx[(long)(m0 + am0) * idxStride] * K;
        aoff1 = (long)idx[(long)(m0 + am0 + 64) * idxStride] * K;
    } else {
        aoff0 = (long)(m0 + am0) * K;
        aoff1 = (long)(m0 + am0 + 64) * K;
    }
    const int  bn     = tid >> 2;
    const bool bvalid = (n0 + bn) < N;
    const long boff   = (long)(n0 + bn) * ldb;

    float acc[2][4][4];
    #pragma unroll
    for (int i = 0; i < 2; i++)
        #pragma unroll
        for (int j = 0; j < 4; j++)
            #pragma unroll
            for (int q = 0; q < 4; q++) acc[i][j][q] = 0.f;

    const int lr = lane >> 2;
    const int lc = lane & 3;

    for (int k0 = 0; k0 < K; k0 += BK) {
        if (k0 + BK <= K) {
            float4 a0 = *(const float4*)(Abase + aoff0 + k0 + ac);
            float4 a1 = *(const float4*)(Abase + aoff1 + k0 + ac);
            float4 bv = bvalid ? *(const float4*)(Bw + boff + k0 + ac)
                               : make_float4(0.f, 0.f, 0.f, 0.f);
            *(uint4*)&As[am0][ac]      = cvt4(a0);
            *(uint4*)&As[am0 + 64][ac] = cvt4(a1);
            *(uint4*)&Bs[bn][ac]       = cvt4(bv);
        } else {
            #pragma unroll
            for (int u = 0; u < 4; u++) {
                int k = k0 + ac + u;
                As[am0][ac + u]      = (k < K) ? f2tf32(Abase[aoff0 + k]) : 0u;
                As[am0 + 64][ac + u] = (k < K) ? f2tf32(Abase[aoff1 + k]) : 0u;
                Bs[bn][ac + u]       = (bvalid && k < K) ? f2tf32(Bw[boff + k]) : 0u;
            }
        }
        __syncthreads();
        #pragma unroll
        for (int ks = 0; ks < 2; ks++) {
            const int kb = ks * 8;
            unsigned a[2][4], b[4][2];
            #pragma unroll
            for (int mi = 0; mi < 2; mi++) {
                int r = wm * 32 + mi * 16 + lr;
                a[mi][0] = As[r][kb + lc];
                a[mi][1] = As[r + 8][kb + lc];
                a[mi][2] = As[r][kb + lc + 4];
                a[mi][3] = As[r + 8][kb + lc + 4];
            }
            #pragma unroll
            for (int ni = 0; ni < 4; ni++) {
                int c = wn * 32 + ni * 8 + lr;
                b[ni][0] = Bs[c][kb + lc];
                b[ni][1] = Bs[c][kb + lc + 4];
            }
            #pragma unroll
            for (int mi = 0; mi < 2; mi++)
                #pragma unroll
                for (int ni = 0; ni < 4; ni++)
                    mma8(acc[mi][ni], a[mi], b[ni]);
        }
        __syncthreads();
    }

    #pragma unroll
    for (int mi = 0; mi < 2; mi++) {
        int r = m0 + wm * 32 + mi * 16 + lr;
        #pragma unroll
        for (int ni = 0; ni < 4; ni++) {
            int cb = n0 + wn * 32 + ni * 8 + 2 * lc;
            #pragma unroll
            for (int q = 0; q < 2; q++) {
                int cc = cb + q;
                if (cc >= N) continue;
                float bv = act ? bias[cc] : 0.f;
                float v0 = acc[mi][ni][q]     + bv;
                float v1 = acc[mi][ni][q + 2] + bv;
                if (act) { v0 = lrelu_f(v0); v1 = lrelu_f(v1); }
                Out[(long)r * N + cc]       = v0;
                Out[(long)(r + 8) * N + cc] = v1;
            }
        }
    }
}

// =====================================================================
// Scores + diag mask + column softmax, grid (2, D) = 128 blocks —
// SINGLE WAVE on 148 SMs. Block (jb,d) -> A[d, :, jb*32 .. jb*32+32].
// Whole K resident in smem (124 KB). 8 warps: wm in 0..3 (rows),
// wn in 0..1 (16-col halves), 2 mma n-tiles per warp.
// =====================================================================
#define SPAD 308
#define SCORES_SMEM ((64 * SPAD + 32 * SPAD + 64 * 33) * 4)   // 126,720 B

__global__ __launch_bounds__(256)
void scores_kernel(const float* __restrict__ P,
                   const float* __restrict__ Cm,
                   float* __restrict__ A_out)
{
    extern __shared__ unsigned sdyn[];
    unsigned* Pt = sdyn;                       // [64][SPAD]
    unsigned* Ct = sdyn + 64 * SPAD;           // [32][SPAD]
    float*    Sh = (float*)(sdyn + 96 * SPAD); // [64][33]

    const int d  = blockIdx.y;
    const int j0 = blockIdx.x * 32;
    const int t = threadIdx.x;
    const int lane = t & 31;
    const int wid  = t >> 5;
    const int wm = wid >> 1;    // 0..3 (row quarter)
    const int wn = wid & 1;     // 0..1 (16-col half)
    const int lr = lane >> 2, lc = lane & 3;

    const float4* Pd4 = (const float4*)(P  + (long)d * S * H);   // 75 float4 per row
    const float4* Cd4 = (const float4*)(Cm + (long)d * S * H);

    // load P whole tile: 64 rows x 76 float4 (75 data + 1 zero pad to k=304)
    for (int u = t; u < 64 * 76; u += 256) {
        int r = u / 76, c4 = u - r * 76;
        float4 v = make_float4(0.f, 0.f, 0.f, 0.f);
        if (c4 < 75) v = Pd4[r * 75 + c4];
        *(uint4*)&Pt[r * SPAD + c4 * 4] = cvt4(v);
    }
    // load C slab: 32 rows (j0..j0+31)
    for (int u = t; u < 32 * 76; u += 256) {
        int r = u / 76, c4 = u - r * 76;
        float4 v = make_float4(0.f, 0.f, 0.f, 0.f);
        if (c4 < 75) v = Cd4[(j0 + r) * 75 + c4];
        *(uint4*)&Ct[r * SPAD + c4 * 4] = cvt4(v);
    }
    __syncthreads();

    float acc[2][4] = {};
    {
        const int r = wm * 16 + lr;
        #pragma unroll 2
        for (int ks = 0; ks < 38; ks++) {
            const int kb = ks * 8;
            unsigned a[4];
            a[0] = Pt[r * SPAD + kb + lc];
            a[1] = Pt[(r + 8) * SPAD + kb + lc];
            a[2] = Pt[r * SPAD + kb + lc + 4];
            a[3] = Pt[(r + 8) * SPAD + kb + lc + 4];
            #pragma unroll
            for (int ni = 0; ni < 2; ni++) {
                unsigned b[2];
                int c = wn * 16 + ni * 8 + lr;
                b[0] = Ct[c * SPAD + kb + lc];
                b[1] = Ct[c * SPAD + kb + lc + 4];
                mma8(acc[ni], a, b);
            }
        }
    }

    // masked scatter into shared
    {
        int r = wm * 16 + lr;
        #pragma unroll
        for (int ni = 0; ni < 2; ni++) {
            int cb = wn * 16 + ni * 8 + 2 * lc;
            int gc = j0 + cb;
            Sh[r * 33 + cb]           = (r == gc)         ? NEGV : acc[ni][0];
            Sh[r * 33 + cb + 1]       = (r == gc + 1)     ? NEGV : acc[ni][1];
            Sh[(r + 8) * 33 + cb]     = (r + 8 == gc)     ? NEGV : acc[ni][2];
            Sh[(r + 8) * 33 + cb + 1] = (r + 8 == gc + 1) ? NEGV : acc[ni][3];
        }
    }
    __syncthreads();

    // warp-parallel column softmax: warp w handles local cols 4w..4w+3
    #pragma unroll
    for (int cc = 0; cc < 4; cc++) {
        int c = wid * 4 + cc;
        float v0 = Sh[lane * 33 + c];
        float v1 = Sh[(lane + 32) * 33 + c];
        float m = fmaxf(v0, v1);
        #pragma unroll
        for (int o = 16; o; o >>= 1) m = fmaxf(m, __shfl_xor_sync(0xffffffffu, m, o));
        float e0 = __expf(v0 - m), e1 = __expf(v1 - m);
        float s = e0 + e1;
        #pragma unroll
        for (int o = 16; o; o >>= 1) s += __shfl_xor_sync(0xffffffffu, s, o);
        float inv = 1.f / s;
        Sh[lane * 33 + c]        = e0 * inv;
        Sh[(lane + 32) * 33 + c] = e1 * inv;
    }
    __syncthreads();

    // write 64 rows x 32 contiguous cols
    for (int u = t; u < 64 * 32; u += 256) {
        int i = u >> 5, j = u & 31;
        A_out[(long)d * 4096 + i * 64 + j0 + j] = Sh[i * 33 + j];
    }
}

// =====================================================================
// G[d,i,h] = sum_k A[d,k,i] * Y2[d*64+k, h]  (tf32 mma), grid (5, D).
// Block x==0 additionally computes rs[d,:]; x==1 computes fri[d,:].
// =====================================================================
__global__ __launch_bounds__(256)
void g_kernel(const float* __restrict__ A_in,
              const float* __restrict__ Y2,
              const float* __restrict__ enc,
              const float* __restrict__ w_root,
              const float* __restrict__ b_root,
              float* __restrict__ G,
              float* __restrict__ rs_out,
              float* __restrict__ fri_out)
{
    const int d  = blockIdx.y;
    const int h0 = blockIdx.x * 64;
    const int t = threadIdx.x;
    const int lane = t & 31;
    const int wid  = t >> 5;
    const int wm = wid >> 1, wn = wid & 1;
    const int lr = lane >> 2, lc = lane & 3;

    __shared__ __align__(16) unsigned Ak[64][65];   // Ak[k][i]
    __shared__ __align__(16) unsigned Ys[64][65];   // Ys[k][h]
    __shared__ float sred[64];

    const float* Ad = A_in + (long)d * 4096;
    const float* Yd = Y2 + (long)d * 64 * H;
    const float* Ed = enc + (long)d * S * H;

    for (int u = t; u < 1024; u += 256) {
        float4 v = ((const float4*)Ad)[u];
        int k = u >> 4, i = (u & 15) * 4;
        Ak[k][i]     = f2tf32(v.x);
        Ak[k][i + 1] = f2tf32(v.y);
        Ak[k][i + 2] = f2tf32(v.z);
        Ak[k][i + 3] = f2tf32(v.w);
    }
    for (int u = t; u < 1024; u += 256) {
        int k = u >> 4, i = (u & 15) * 4;
        int h = h0 + i;
        float4 v = make_float4(0.f, 0.f, 0.f, 0.f);
        if (h < H) v = *(const float4*)(Yd + k * H + h);
        Ys[k][i]     = f2tf32(v.x);
        Ys[k][i + 1] = f2tf32(v.y);
        Ys[k][i + 2] = f2tf32(v.z);
        Ys[k][i + 3] = f2tf32(v.w);
    }
    __syncthreads();

    float acc[4][4] = {};
    #pragma unroll
    for (int ks = 0; ks < 8; ks++) {
        const int kb = ks * 8;
        unsigned a[4], b[4][2];
        int r = wm * 16 + lr;
        a[0] = Ak[kb + lc][r];
        a[1] = Ak[kb + lc][r + 8];
        a[2] = Ak[kb + lc + 4][r];
        a[3] = Ak[kb + lc + 4][r + 8];
        #pragma unroll
        for (int ni = 0; ni < 4; ni++) {
            int c = wn * 32 + ni * 8 + lr;
            b[ni][0] = Ys[kb + lc][c];
            b[ni][1] = Ys[kb + lc + 4][c];
        }
        #pragma unroll
        for (int ni = 0; ni < 4; ni++)
            mma8(acc[ni], a, b[ni]);
    }

    {
        int r = wm * 16 + lr;
        #pragma unroll
        for (int ni = 0; ni < 4; ni++) {
            int cb = wn * 32 + ni * 8 + 2 * lc;
            #pragma unroll
            for (int q = 0; q < 2; q++) {
                int h = h0 + cb + q;
                if (h >= H) continue;
                G[(long)(d * 64 + r) * H + h]     = acc[ni][q];
                G[(long)(d * 64 + r + 8) * H + h] = acc[ni][q + 2];
            }
        }
    }

    if (blockIdx.x == 0) {
        #pragma unroll
        for (int rr = 0; rr < 8; rr++) {
            int r = wid * 8 + rr;
            float s = Ad[r * 64 + lane] + Ad[r * 64 + lane + 32];
            #pragma unroll
            for (int o = 16; o; o >>= 1) s += __shfl_xor_sync(0xffffffffu, s, o);
            if (lane == 0) rs_out[d * 64 + r] = s;
        }
    } else if (blockIdx.x == 1) {
        const float br0 = b_root[0];
        #pragma unroll
        for (int ss = 0; ss < 8; ss++) {
            int s = wid * 8 + ss;
            const float* e = Ed + s * H;
            float p = 0.f;
            for (int h = lane; h < H; h += 32) p += e[h] * w_root[h];
            #pragma unroll
            for (int o = 16; o; o >>= 1) p += __shfl_xor_sync(0xffffffffu, p, o);
            if (lane == 0) sred[s] = p + br0;
        }
        __syncthreads();
        float mye = 0.f;
        if (t < 64) {
            float m = -1e30f;
            for (int u = 0; u < 64; u++) m = fmaxf(m, sred[u]);
            mye = __expf(sred[t] - m);
        }
        __syncthreads();
        if (t < 64) sred[t] = mye;
        __syncthreads();
        if (t < 64) {
            float ssum = 0.f;
            for (int u = 0; u < 64; u++) ssum += sred[u];
            fri_out[d * 64 + t] = mye / ssum;
        }
    }
}

// =====================================================================
// ri+mean: fin[doc,n] = mean_s lrelu( enc@W1^T + rs*(enc@W3^T)
//                                     + G + fri*v2 + b_r )
// (R5-proven single-buffer version.)
// =====================================================================
__global__ __launch_bounds__(256)
void ri_mean_kernel(const float* __restrict__ enc,
                    const float* __restrict__ W_r,   // [H, 900]
                    const float* __restrict__ b_r,
                    const float* __restrict__ G,
                    const float* __restrict__ rs,
                    const float* __restrict__ fri,
                    const float* __restrict__ v2,
                    float* __restrict__ fin)
{
    __shared__ __align__(16) unsigned As[BM][BKP];
    __shared__ __align__(16) unsigned B1s[BN][BKP];
    __shared__ __align__(16) unsigned B3s[BN][BKP];
    __shared__ float red[2][BN];

    const int K = H;
    const int N = H;
    const int tid  = threadIdx.x;
    const int lane = tid & 31;
    const int wid  = tid >> 5;
    const int wm = wid >> 1, wn = wid & 1;
    const int m0 = blockIdx.y * BM;
    const int n0 = blockIdx.x * BN;

    if (tid < 2 * BN) ((float*)red)[tid] = 0.f;

    const int am0 = tid >> 2;
    const int ac  = (tid & 3) * 4;
    const long aoff0 = (long)(m0 + am0) * K;
    const long aoff1 = (long)(m0 + am0 + 64) * K;
    const int  bn     = tid >> 2;
    const bool bvalid = (n0 + bn) < N;
    const long boff   = (long)(n0 + bn) * 900;

    float acc1[2][4][4], acc3[2][4][4];
    #pragma unroll
    for (int i = 0; i < 2; i++)
        #pragma unroll
        for (int j = 0; j < 4; j++)
            #pragma unroll
            for (int q = 0; q < 4; q++) { acc1[i][j][q] = 0.f; acc3[i][j][q] = 0.f; }

    const int lr = lane >> 2, lc = lane & 3;

    for (int k0 = 0; k0 < K; k0 += BK) {
        if (k0 + BK <= K) {
            float4 a0 = *(const float4*)(enc + aoff0 + k0 + ac);
            float4 a1 = *(const float4*)(enc + aoff1 + k0 + ac);
            float4 b1 = bvalid ? *(const float4*)(W_r + boff + k0 + ac) : make_float4(0,0,0,0);
            float4 b3 = bvalid ? *(const float4*)(W_r + boff + 600 + k0 + ac) : make_float4(0,0,0,0);
            *(uint4*)&As[am0][ac]      = cvt4(a0);
            *(uint4*)&As[am0 + 64][ac] = cvt4(a1);
            *(uint4*)&B1s[bn][ac]      = cvt4(b1);
            *(uint4*)&B3s[bn][ac]      = cvt4(b3);
        } else {
            #pragma unroll
            for (int u = 0; u < 4; u++) {
                int k = k0 + ac + u;
                bool kk = k < K;
                As[am0][ac + u]      = kk ? f2tf32(enc[aoff0 + k]) : 0u;
                As[am0 + 64][ac + u] = kk ? f2tf32(enc[aoff1 + k]) : 0u;
                B1s[bn][ac + u]      = (bvalid && kk) ? f2tf32(W_r[boff + k]) : 0u;
                B3s[bn][ac + u]      = (bvalid && kk) ? f2tf32(W_r[boff + 600 + k]) : 0u;
            }
        }
        __syncthreads();
        #pragma unroll
        for (int ks = 0; ks < 2; ks++) {
            const int kb = ks * 8;
            unsigned a[2][4], b1[4][2], b3[4][2];
            #pragma unroll
            for (int mi = 0; mi < 2; mi++) {
                int r = wm * 32 + mi * 16 + lr;
                a[mi][0] = As[r][kb + lc];
                a[mi][1] = As[r + 8][kb + lc];
                a[mi][2] = As[r][kb + lc + 4];
                a[mi][3] = As[r + 8][kb + lc + 4];
            }
            #pragma unroll
            for (int ni = 0; ni < 4; ni++) {
                int c = wn * 32 + ni * 8 + lr;
                b1[ni][0] = B1s[c][kb + lc];
                b1[ni][1] = B1s[c][kb + lc + 4];
                b3[ni][0] = B3s[c][kb + lc];
                b3[ni][1] = B3s[c][kb + lc + 4];
            }
            #pragma unroll
            for (int mi = 0; mi < 2; mi++)
                #pragma unroll
                for (int ni = 0; ni < 4; ni++) {
                    mma8(acc1[mi][ni], a[mi], b1[ni]);
                    mma8(acc3[mi][ni], a[mi], b3[ni]);
                }
        }
        __syncthreads();
    }

    const int dl = wm >> 1;
    #pragma unroll
    for (int ni = 0; ni < 4; ni++) {
        int cb = n0 + wn * 32 + ni * 8 + 2 * lc;
        float s0 = 0.f, s1 = 0.f;
        #pragma unroll
        for (int mi = 0; mi < 2; mi++) {
            int r = m0 + wm * 32 + mi * 16 + lr;
            #pragma unroll
            for (int half = 0; half < 2; half++) {
                int m = r + half * 8;
                float rsm = rs[m], frm = fri[m];
                if (cb < N) {
                    float v = acc1[mi][ni][half * 2] + rsm * acc3[mi][ni][half * 2]
                            + G[(long)m * H + cb] + frm * v2[cb] + b_r[cb];
                    s0 += lrelu_f(v);
                }
                if (cb + 1 < N) {
                    float v = acc1[mi][ni][half * 2 + 1] + rsm * acc3[mi][ni][half * 2 + 1]
                            + G[(long)m * H + cb + 1] + frm * v2[cb + 1] + b_r[cb + 1];
                    s1 += lrelu_f(v);
                }
            }
        }
        #pragma unroll
        for (int o = 4; o < 32; o <<= 1) {
            s0 += __shfl_xor_sync(0xffffffffu, s0, o);
            s1 += __shfl_xor_sync(0xffffffffu, s1, o);
        }
        if (lane < 4) {
            atomicAdd(&red[dl][wn * 32 + ni * 8 + 2 * lc],     s0);
            atomicAdd(&red[dl][wn * 32 + ni * 8 + 2 * lc + 1], s1);
        }
    }
    __syncthreads();
    if (tid < 128) {
        int dloc = tid >> 6, c = tid & 63;
        int col = n0 + c;
        if (col < N)
            fin[(long)(blockIdx.y * 2 + dloc) * H + col] = red[dloc][c] * (1.f / 64.f);
    }
}

// v2[n] = sum_k W_r[n, 300+k] * root_embed[k]
__global__ void v2_kernel(const float* __restrict__ W_r,
                          const float* __restrict__ root_embed,
                          float* __restrict__ v2)
{
    int wid = threadIdx.x >> 5, lane = threadIdx.x & 31;
    int n = blockIdx.x * 8 + wid;
    if (n >= H) return;
    const float* w = W_r + (long)n * 900 + 300;
    float p = 0.f;
    for (int k = lane; k < H; k += 32) p += w[k] * root_embed[k];
    #pragma unroll
    for (int o = 16; o; o >>= 1) p += __shfl_xor_sync(0xffffffffu, p, o);
    if (lane == 0) v2[n] = p;
}

// out[d,c]: one warp per output
__global__ void cls_kernel(const float* __restrict__ fin,
                           const float* __restrict__ Wc,
                           const float* __restrict__ bc,
                           float* __restrict__ out)
{
    int gw = blockIdx.x * (blockDim.x >> 5) + (threadIdx.x >> 5);
    int lane = threadIdx.x & 31;
    if (gw >= 128) return;
    int d = gw >> 1, c = gw & 1;
    const float* f = fin + d * H;
    const float* w = Wc + c * H;
    float p = 0.f;
    for (int h = lane; h < H; h += 32) p += f[h] * w[h];
    #pragma unroll
    for (int o = 16; o; o >>= 1) p += __shfl_xor_sync(0xffffffffu, p, o);
    if (lane == 0) out[d * 2 + c] = p + bc[c];
}

// =====================================================================
extern "C" void kernel_launch(void* const* d_in, const int* in_sizes, int n_in,
                              void* d_out, int out_size)
{
    const int*   word_indices = (const int*)  d_in[0];
    const float* E            = (const float*)d_in[1];
    const float* W_sent       = (const float*)d_in[2];
    const float* b_sent       = (const float*)d_in[3];
    const float* W_par        = (const float*)d_in[4];
    const float* b_par        = (const float*)d_in[5];
    const float* W_ch         = (const float*)d_in[6];
    const float* b_ch         = (const float*)d_in[7];
    const float* w_root       = (const float*)d_in[8];
    const float* b_root       = (const float*)d_in[9];
    const float* root_embed   = (const float*)d_in[10];
    const float* W_r          = (const float*)d_in[11];
    const float* b_r          = (const float*)d_in[12];
    const float* W_cls        = (const float*)d_in[13];
    const float* b_cls        = (const float*)d_in[14];

    float* out_ptr = (float*)d_out;
    float* A_ptr   = out_ptr + D * 2;
    float* fri_ptr = A_ptr + D * S * S;

    float *enc, *Pm, *Cm, *Y2, *G, *rs, *fin, *v2;
    cudaGetSymbolAddress((void**)&enc, g_enc);
    cudaGetSymbolAddress((void**)&Pm,  g_P);
    cudaGetSymbolAddress((void**)&Cm,  g_C);
    cudaGetSymbolAddress((void**)&Y2,  g_Y2);
    cudaGetSymbolAddress((void**)&G,   g_G);
    cudaGetSymbolAddress((void**)&rs,  g_rs);
    cudaGetSymbolAddress((void**)&fin, g_fin);
    cudaGetSymbolAddress((void**)&v2,  g_v2);

    cudaFuncSetAttribute(scores_kernel,
                         cudaFuncAttributeMaxDynamicSharedMemorySize, SCORES_SMEM);

    v2_kernel<<<(H + 7) / 8, 256>>>(W_r, root_embed, v2);

    dim3 gEnc((H + BN - 1) / BN, NROWS / BM, 1);
    gemm_tf32_kernel<true><<<gEnc, 256>>>(
        E, word_indices + (L - 1), L,
        W_sent, b_sent, enc,
        nullptr, nullptr, nullptr,
        nullptr, nullptr, nullptr, H, W, W, W, W);

    // P, C (lrelu+bias) and Y2 = enc @ W2^T (linear; W2 rows inside W_r, ld=900)
    dim3 gPCY((H + BN - 1) / BN, NROWS / BM, 3);
    gemm_tf32_kernel<false><<<gPCY, 256>>>(
        enc, nullptr, 0,
        W_par,       b_par,   Pm,
        W_ch,        b_ch,    Cm,
        W_r + 300,   nullptr, Y2,
        H, H, H, H, 900);

    // scores + mask + column softmax -> A (in d_out); single wave (128 blocks)
    scores_kernel<<<dim3(2, D), 256, SCORES_SMEM>>>(Pm, Cm, A_ptr);

    // G = A^T @ Y2 per doc; also rs (x==0) and fri (x==1)
    g_kernel<<<dim3(5, D), 256>>>(A_ptr, Y2, enc, w_root, b_root, G, rs, fri_ptr);

    ri_mean_kernel<<<dim3(5, 32), 256>>>(enc, W_r, b_r, G, rs, fri_ptr, v2, fin);

    cls_kernel<<<8, 512>>>(fin, W_cls, b_cls, out_ptr);
}

// round 8
// speedup vs baseline: 1.5113x; 1.5113x over previous
#include <cuda_runtime.h>

#define D 64
#define S 64
#define L 64
#define W 300
#define H 300
#define NROWS (D*S)          // 4096
#define NEGV (-9999999.0f)

// ---------------- device scratch (no allocation allowed) ----------------
__device__ float g_enc[NROWS * H];
__device__ float g_P  [NROWS * H];
__device__ float g_C  [NROWS * H];
__device__ float g_Y2 [NROWS * H];
__device__ float g_G  [NROWS * H];
__device__ float g_rs [NROWS];
__device__ float g_fin[D * H];
__device__ float g_v2 [H];

__device__ __forceinline__ float lrelu_f(float x) { return x > 0.f ? x : 0.01f * x; }

__device__ __forceinline__ unsigned f2tf32(float f) {
    unsigned u;
    asm("cvt.rna.tf32.f32 %0, %1;" : "=r"(u) : "f"(f));
    return u;
}
__device__ __forceinline__ uint4 cvt4(float4 v) {
    return make_uint4(f2tf32(v.x), f2tf32(v.y), f2tf32(v.z), f2tf32(v.w));
}

__device__ __forceinline__ void mma8(float* c, const unsigned* a, const unsigned* b) {
    asm volatile(
        "mma.sync.aligned.m16n8k8.row.col.f32.tf32.tf32.f32 "
        "{%0,%1,%2,%3}, {%4,%5,%6,%7}, {%8,%9}, {%0,%1,%2,%3};"
        : "+f"(c[0]), "+f"(c[1]), "+f"(c[2]), "+f"(c[3])
        : "r"(a[0]), "r"(a[1]), "r"(a[2]), "r"(a[3]), "r"(b[0]), "r"(b[1]));
}

#define BM 128
#define BN 64
#define BK 16
#define BKP 20

// =====================================================================
// TF32 GEMM (R5-proven): Out[M,N] = act( A[M,K] @ B[N,K(ld=ldb)]^T + b )
// z selects among 3 (B,bias,Out) triples; bias==nullptr => linear.
// =====================================================================
template<bool GATHER>
__global__ void gemm_tf32_kernel(
    const float* __restrict__ Abase, const int* __restrict__ idx, int idxStride,
    const float* __restrict__ B0, const float* __restrict__ bias0, float* __restrict__ Out0,
    const float* __restrict__ B1, const float* __restrict__ bias1, float* __restrict__ Out1,
    const float* __restrict__ B2, const float* __restrict__ bias2, float* __restrict__ Out2,
    int N, int K, int ldb0, int ldb1, int ldb2)
{
    const float* Bw   = B0;
    const float* bias = bias0;
    float*       Out  = Out0;
    int          ldb  = ldb0;
    if (blockIdx.z == 1) { Bw = B1; bias = bias1; Out = Out1; ldb = ldb1; }
    if (blockIdx.z == 2) { Bw = B2; bias = bias2; Out = Out2; ldb = ldb2; }
    const bool act = (bias != nullptr);

    __shared__ __align__(16) unsigned As[BM][BKP];
    __shared__ __align__(16) unsigned Bs[BN][BKP];

    const int tid  = threadIdx.x;
    const int lane = tid & 31;
    const int wid  = tid >> 5;
    const int wm   = wid >> 1;
    const int wn   = wid & 1;
    const int m0   = blockIdx.y * BM;
    const int n0   = blockIdx.x * BN;

    const int am0 = tid >> 2;
    const int ac  = (tid & 3) * 4;
    long aoff0, aoff1;
    if (GATHER) {
        aoff0 = (long)idx[(long)(m0 + am0) * idxStride] * K;
        aoff1 = (long)idx[(long)(m0 + am0 + 64) * idxStride] * K;
    } else {
        aoff0 = (long)(m0 + am0) * K;
        aoff1 = (long)(m0 + am0 + 64) * K;
    }
    const int  bn     = tid >> 2;
    const bool bvalid = (n0 + bn) < N;
    const long boff   = (long)(n0 + bn) * ldb;

    float acc[2][4][4];
    #pragma unroll
    for (int i = 0; i < 2; i++)
        #pragma unroll
        for (int j = 0; j < 4; j++)
            #pragma unroll
            for (int q = 0; q < 4; q++) acc[i][j][q] = 0.f;

    const int lr = lane >> 2;
    const int lc = lane & 3;

    for (int k0 = 0; k0 < K; k0 += BK) {
        if (k0 + BK <= K) {
            float4 a0 = *(const float4*)(Abase + aoff0 + k0 + ac);
            float4 a1 = *(const float4*)(Abase + aoff1 + k0 + ac);
            float4 bv = bvalid ? *(const float4*)(Bw + boff + k0 + ac)
                               : make_float4(0.f, 0.f, 0.f, 0.f);
            *(uint4*)&As[am0][ac]      = cvt4(a0);
            *(uint4*)&As[am0 + 64][ac] = cvt4(a1);
            *(uint4*)&Bs[bn][ac]       = cvt4(bv);
        } else {
            #pragma unroll
            for (int u = 0; u < 4; u++) {
                int k = k0 + ac + u;
                As[am0][ac + u]      = (k < K) ? f2tf32(Abase[aoff0 + k]) : 0u;
                As[am0 + 64][ac + u] = (k < K) ? f2tf32(Abase[aoff1 + k]) : 0u;
                Bs[bn][ac + u]       = (bvalid && k < K) ? f2tf32(Bw[boff + k]) : 0u;
            }
        }
        __syncthreads();
        #pragma unroll
        for (int ks = 0; ks < 2; ks++) {
            const int kb = ks * 8;
            unsigned a[2][4], b[4][2];
            #pragma unroll
            for (int mi = 0; mi < 2; mi++) {
                int r = wm * 32 + mi * 16 + lr;
                a[mi][0] = As[r][kb + lc];
                a[mi][1] = As[r + 8][kb + lc];
                a[mi][2] = As[r][kb + lc + 4];
                a[mi][3] = As[r + 8][kb + lc + 4];
            }
            #pragma unroll
            for (int ni = 0; ni < 4; ni++) {
                int c = wn * 32 + ni * 8 + lr;
                b[ni][0] = Bs[c][kb + lc];
                b[ni][1] = Bs[c][kb + lc + 4];
            }
            #pragma unroll
            for (int mi = 0; mi < 2; mi++)
                #pragma unroll
                for (int ni = 0; ni < 4; ni++)
                    mma8(acc[mi][ni], a[mi], b[ni]);
        }
        __syncthreads();
    }

    #pragma unroll
    for (int mi = 0; mi < 2; mi++) {
        int r = m0 + wm * 32 + mi * 16 + lr;
        #pragma unroll
        for (int ni = 0; ni < 4; ni++) {
            int cb = n0 + wn * 32 + ni * 8 + 2 * lc;
            #pragma unroll
            for (int q = 0; q < 2; q++) {
                int cc = cb + q;
                if (cc >= N) continue;
                float bv = act ? bias[cc] : 0.f;
                float v0 = acc[mi][ni][q]     + bv;
                float v1 = acc[mi][ni][q + 2] + bv;
                if (act) { v0 = lrelu_f(v0); v1 = lrelu_f(v1); }
                Out[(long)r * N + cc]       = v0;
                Out[(long)(r + 8) * N + cc] = v1;
            }
        }
    }
}

// =====================================================================
// Scores + diag mask + column softmax, grid (4, D), 256 thr (R5-proven:
// 103 KB smem => 2 blocks/SM co-resident, ~single wave).
// Block (jb, d) computes A[d, :, jb*16 : jb*16+16].
// =====================================================================
#define SPAD 308
#define SCORES_SMEM ((80 * SPAD + 64 * 17) * 4)   // 102,912 B

__global__ void scores_kernel(const float* __restrict__ P,
                              const float* __restrict__ Cm,
                              float* __restrict__ A_out)
{
    extern __shared__ unsigned sdyn[];
    unsigned* Pt = sdyn;                       // [64][SPAD]
    unsigned* Ct = sdyn + 64 * SPAD;           // [16][SPAD]
    float*    Sh = (float*)(sdyn + 80 * SPAD); // [64][17]

    const int d  = blockIdx.y;
    const int j0 = blockIdx.x * 16;
    const int t = threadIdx.x;
    const int lane = t & 31;
    const int wid  = t >> 5;
    const int wm = wid >> 1;    // 0..3
    const int wn = wid & 1;     // 0..1
    const int lr = lane >> 2, lc = lane & 3;

    const float4* Pd4 = (const float4*)(P  + (long)d * S * H);   // 75 float4 per row
    const float4* Cd4 = (const float4*)(Cm + (long)d * S * H);

    for (int u = t; u < 64 * 76; u += 256) {
        int r = u / 76, c4 = u - r * 76;
        float4 v = make_float4(0.f, 0.f, 0.f, 0.f);
        if (c4 < 75) v = Pd4[r * 75 + c4];
        *(uint4*)&Pt[r * SPAD + c4 * 4] = cvt4(v);
    }
    for (int u = t; u < 16 * 76; u += 256) {
        int r = u / 76, c4 = u - r * 76;
        float4 v = make_float4(0.f, 0.f, 0.f, 0.f);
        if (c4 < 75) v = Cd4[(j0 + r) * 75 + c4];
        *(uint4*)&Ct[r * SPAD + c4 * 4] = cvt4(v);
    }
    __syncthreads();

    float acc[4] = {};
    {
        const int r = wm * 16 + lr;
        const int c = wn * 8 + lr;
        #pragma unroll
        for (int ks = 0; ks < 38; ks++) {
            const int kb = ks * 8;
            unsigned a[4], b[2];
            a[0] = Pt[r * SPAD + kb + lc];
            a[1] = Pt[(r + 8) * SPAD + kb + lc];
            a[2] = Pt[r * SPAD + kb + lc + 4];
            a[3] = Pt[(r + 8) * SPAD + kb + lc + 4];
            b[0] = Ct[c * SPAD + kb + lc];
            b[1] = Ct[c * SPAD + kb + lc + 4];
            mma8(acc, a, b);
        }
    }

    {
        int r = wm * 16 + lr;
        int cb = wn * 8 + 2 * lc;
        int gc = j0 + cb;
        Sh[r * 17 + cb]           = (r == gc)         ? NEGV : acc[0];
        Sh[r * 17 + cb + 1]       = (r == gc + 1)     ? NEGV : acc[1];
        Sh[(r + 8) * 17 + cb]     = (r + 8 == gc)     ? NEGV : acc[2];
        Sh[(r + 8) * 17 + cb + 1] = (r + 8 == gc + 1) ? NEGV : acc[3];
    }
    __syncthreads();

    #pragma unroll
    for (int cc = 0; cc < 2; cc++) {
        int c = wid * 2 + cc;
        float v0 = Sh[lane * 17 + c];
        float v1 = Sh[(lane + 32) * 17 + c];
        float m = fmaxf(v0, v1);
        #pragma unroll
        for (int o = 16; o; o >>= 1) m = fmaxf(m, __shfl_xor_sync(0xffffffffu, m, o));
        float e0 = __expf(v0 - m), e1 = __expf(v1 - m);
        float s = e0 + e1;
        #pragma unroll
        for (int o = 16; o; o >>= 1) s += __shfl_xor_sync(0xffffffffu, s, o);
        float inv = 1.f / s;
        Sh[lane * 17 + c]        = e0 * inv;
        Sh[(lane + 32) * 17 + c] = e1 * inv;
    }
    __syncthreads();

    for (int u = t; u < 64 * 16; u += 256) {
        int i = u >> 4, j = u & 15;
        A_out[(long)d * 4096 + i * 64 + j0 + j] = Sh[i * 17 + j];
    }
}

// =====================================================================
// G[d,i,h] = sum_k A[d,k,i] * Y2[d*64+k, h]  (tf32 mma), grid (5, D).
// Extras: x==0 -> rs[d,:], x==1 -> fri[d,:], x==2 -> v2 slice (5 cols/d).
// =====================================================================
__global__ void g_kernel(const float* __restrict__ A_in,
                         const float* __restrict__ Y2,
                         const float* __restrict__ enc,
                         const float* __restrict__ w_root,
                         const float* __restrict__ b_root,
                         const float* __restrict__ W_r,
                         const float* __restrict__ root_embed,
                         float* __restrict__ G,
                         float* __restrict__ rs_out,
                         float* __restrict__ fri_out,
                         float* __restrict__ v2_out)
{
    const int d  = blockIdx.y;
    const int h0 = blockIdx.x * 64;
    const int t = threadIdx.x;
    const int lane = t & 31;
    const int wid  = t >> 5;
    const int wm = wid >> 1, wn = wid & 1;
    const int lr = lane >> 2, lc = lane & 3;

    __shared__ __align__(16) unsigned Ak[64][65];   // Ak[k][i]
    __shared__ __align__(16) unsigned Ys[64][65];   // Ys[k][h]
    __shared__ float sred[64];

    const float* Ad = A_in + (long)d * 4096;
    const float* Yd = Y2 + (long)d * 64 * H;
    const float* Ed = enc + (long)d * S * H;

    for (int u = t; u < 1024; u += 256) {
        float4 v = ((const float4*)Ad)[u];
        int k = u >> 4, i = (u & 15) * 4;
        Ak[k][i]     = f2tf32(v.x);
        Ak[k][i + 1] = f2tf32(v.y);
        Ak[k][i + 2] = f2tf32(v.z);
        Ak[k][i + 3] = f2tf32(v.w);
    }
    for (int u = t; u < 1024; u += 256) {
        int k = u >> 4, i = (u & 15) * 4;
        int h = h0 + i;
        float4 v = make_float4(0.f, 0.f, 0.f, 0.f);
        if (h < H) v = *(const float4*)(Yd + k * H + h);
        Ys[k][i]     = f2tf32(v.x);
        Ys[k][i + 1] = f2tf32(v.y);
        Ys[k][i + 2] = f2tf32(v.z);
        Ys[k][i + 3] = f2tf32(v.w);
    }
    __syncthreads();

    float acc[4][4] = {};
    #pragma unroll
    for (int ks = 0; ks < 8; ks++) {
        const int kb = ks * 8;
        unsigned a[4], b[4][2];
        int r = wm * 16 + lr;
        a[0] = Ak[kb + lc][r];
        a[1] = Ak[kb + lc][r + 8];
        a[2] = Ak[kb + lc + 4][r];
        a[3] = Ak[kb + lc + 4][r + 8];
        #pragma unroll
        for (int ni = 0; ni < 4; ni++) {
            int c = wn * 32 + ni * 8 + lr;
            b[ni][0] = Ys[kb + lc][c];
            b[ni][1] = Ys[kb + lc + 4][c];
        }
        #pragma unroll
        for (int ni = 0; ni < 4; ni++)
            mma8(acc[ni], a, b[ni]);
    }

    {
        int r = wm * 16 + lr;
        #pragma unroll
        for (int ni = 0; ni < 4; ni++) {
            int cb = wn * 32 + ni * 8 + 2 * lc;
            #pragma unroll
            for (int q = 0; q < 2; q++) {
                int h = h0 + cb + q;
                if (h >= H) continue;
                G[(long)(d * 64 + r) * H + h]     = acc[ni][q];
                G[(long)(d * 64 + r + 8) * H + h] = acc[ni][q + 2];
            }
        }
    }

    if (blockIdx.x == 0) {
        #pragma unroll
        for (int rr = 0; rr < 8; rr++) {
            int r = wid * 8 + rr;
            float s = Ad[r * 64 + lane] + Ad[r * 64 + lane + 32];
            #pragma unroll
            for (int o = 16; o; o >>= 1) s += __shfl_xor_sync(0xffffffffu, s, o);
            if (lane == 0) rs_out[d * 64 + r] = s;
        }
    } else if (blockIdx.x == 1) {
        const float br0 = b_root[0];
        #pragma unroll
        for (int ss = 0; ss < 8; ss++) {
            int s = wid * 8 + ss;
            const float* e = Ed + s * H;
            float p = 0.f;
            for (int h = lane; h < H; h += 32) p += e[h] * w_root[h];
            #pragma unroll
            for (int o = 16; o; o >>= 1) p += __shfl_xor_sync(0xffffffffu, p, o);
            if (lane == 0) sred[s] = p + br0;
        }
        __syncthreads();
        float mye = 0.f;
        if (t < 64) {
            float m = -1e30f;
            for (int u = 0; u < 64; u++) m = fmaxf(m, sred[u]);
            mye = __expf(sred[t] - m);
        }
        __syncthreads();
        if (t < 64) sred[t] = mye;
        __syncthreads();
        if (t < 64) {
            float ssum = 0.f;
            for (int u = 0; u < 64; u++) ssum += sred[u];
            fri_out[d * 64 + t] = mye / ssum;
        }
    } else if (blockIdx.x == 2) {
        // v2[n] = W_r[n, 300:600] . root_embed  — this d handles n = d*5..d*5+4
        if (wid < 5) {
            int n = d * 5 + wid;
            if (n < H) {
                const float* w = W_r + (long)n * 900 + 300;
                float p = 0.f;
                for (int k = lane; k < H; k += 32) p += w[k] * root_embed[k];
                #pragma unroll
                for (int o = 16; o; o >>= 1) p += __shfl_xor_sync(0xffffffffu, p, o);
                if (lane == 0) v2_out[n] = p;
            }
        }
    }
}

// =====================================================================
// ri+mean: fin[doc,n] = mean_s lrelu( enc@W1^T + rs*(enc@W3^T)
//                                     + G + fri*v2 + b_r )   (R5-proven)
// =====================================================================
__global__ void ri_mean_kernel(const float* __restrict__ enc,
                               const float* __restrict__ W_r,   // [H, 900]
                               const float* __restrict__ b_r,
                               const float* __restrict__ G,
                               const float* __restrict__ rs,
                               const float* __restrict__ fri,
                               const float* __restrict__ v2,
                               float* __restrict__ fin)
{
    __shared__ __align__(16) unsigned As[BM][BKP];
    __shared__ __align__(16) unsigned B1s[BN][BKP];
    __shared__ __align__(16) unsigned B3s[BN][BKP];
    __shared__ float red[2][BN];

    const int K = H;
    const int N = H;
    const int tid  = threadIdx.x;
    const int lane = tid & 31;
    const int wid  = tid >> 5;
    const int wm = wid >> 1, wn = wid & 1;
    const int m0 = blockIdx.y * BM;
    const int n0 = blockIdx.x * BN;

    if (tid < 2 * BN) ((float*)red)[tid] = 0.f;

    const int am0 = tid >> 2;
    const int ac  = (tid & 3) * 4;
    const long aoff0 = (long)(m0 + am0) * K;
    const long aoff1 = (long)(m0 + am0 + 64) * K;
    const int  bn     = tid >> 2;
    const bool bvalid = (n0 + bn) < N;
    const long boff   = (long)(n0 + bn) * 900;

    float acc1[2][4][4], acc3[2][4][4];
    #pragma unroll
    for (int i = 0; i < 2; i++)
        #pragma unroll
        for (int j = 0; j < 4; j++)
            #pragma unroll
            for (int q = 0; q < 4; q++) { acc1[i][j][q] = 0.f; acc3[i][j][q] = 0.f; }

    const int lr = lane >> 2, lc = lane & 3;

    for (int k0 = 0; k0 < K; k0 += BK) {
        if (k0 + BK <= K) {
            float4 a0 = *(const float4*)(enc + aoff0 + k0 + ac);
            float4 a1 = *(const float4*)(enc + aoff1 + k0 + ac);
            float4 b1 = bvalid ? *(const float4*)(W_r + boff + k0 + ac) : make_float4(0,0,0,0);
            float4 b3 = bvalid ? *(const float4*)(W_r + boff + 600 + k0 + ac) : make_float4(0,0,0,0);
            *(uint4*)&As[am0][ac]      = cvt4(a0);
            *(uint4*)&As[am0 + 64][ac] = cvt4(a1);
            *(uint4*)&B1s[bn][ac]      = cvt4(b1);
            *(uint4*)&B3s[bn][ac]      = cvt4(b3);
        } else {
            #pragma unroll
            for (int u = 0; u < 4; u++) {
                int k = k0 + ac + u;
                bool kk = k < K;
                As[am0][ac + u]      = kk ? f2tf32(enc[aoff0 + k]) : 0u;
                As[am0 + 64][ac + u] = kk ? f2tf32(enc[aoff1 + k]) : 0u;
                B1s[bn][ac + u]      = (bvalid && kk) ? f2tf32(W_r[boff + k]) : 0u;
                B3s[bn][ac + u]      = (bvalid && kk) ? f2tf32(W_r[boff + 600 + k]) : 0u;
            }
        }
        __syncthreads();
        #pragma unroll
        for (int ks = 0; ks < 2; ks++) {
            const int kb = ks * 8;
            unsigned a[2][4], b1[4][2], b3[4][2];
            #pragma unroll
            for (int mi = 0; mi < 2; mi++) {
                int r = wm * 32 + mi * 16 + lr;
                a[mi][0] = As[r][kb + lc];
                a[mi][1] = As[r + 8][kb + lc];
                a[mi][2] = As[r][kb + lc + 4];
                a[mi][3] = As[r + 8][kb + lc + 4];
            }
            #pragma unroll
            for (int ni = 0; ni < 4; ni++) {
                int c = wn * 32 + ni * 8 + lr;
                b1[ni][0] = B1s[c][kb + lc];
                b1[ni][1] = B1s[c][kb + lc + 4];
                b3[ni][0] = B3s[c][kb + lc];
                b3[ni][1] = B3s[c][kb + lc + 4];
            }
            #pragma unroll
            for (int mi = 0; mi < 2; mi++)
                #pragma unroll
                for (int ni = 0; ni < 4; ni++) {
                    mma8(acc1[mi][ni], a[mi], b1[ni]);
                    mma8(acc3[mi][ni], a[mi], b3[ni]);
                }
        }
        __syncthreads();
    }

    const int dl = wm >> 1;
    #pragma unroll
    for (int ni = 0; ni < 4; ni++) {
        int cb = n0 + wn * 32 + ni * 8 + 2 * lc;
        float s0 = 0.f, s1 = 0.f;
        #pragma unroll
        for (int mi = 0; mi < 2; mi++) {
            int r = m0 + wm * 32 + mi * 16 + lr;
            #pragma unroll
            for (int half = 0; half < 2; half++) {
                int m = r + half * 8;
                float rsm = rs[m], frm = fri[m];
                if (cb < N) {
                    float v = acc1[mi][ni][half * 2] + rsm * acc3[mi][ni][half * 2]
                            + G[(long)m * H + cb] + frm * v2[cb] + b_r[cb];
                    s0 += lrelu_f(v);
                }
                if (cb + 1 < N) {
                    float v = acc1[mi][ni][half * 2 + 1] + rsm * acc3[mi][ni][half * 2 + 1]
                            + G[(long)m * H + cb + 1] + frm * v2[cb + 1] + b_r[cb + 1];
                    s1 += lrelu_f(v);
                }
            }
        }
        #pragma unroll
        for (int o = 4; o < 32; o <<= 1) {
            s0 += __shfl_xor_sync(0xffffffffu, s0, o);
            s1 += __shfl_xor_sync(0xffffffffu, s1, o);
        }
        if (lane < 4) {
            atomicAdd(&red[dl][wn * 32 + ni * 8 + 2 * lc],     s0);
            atomicAdd(&red[dl][wn * 32 + ni * 8 + 2 * lc + 1], s1);
        }
    }
    __syncthreads();
    if (tid < 128) {
        int dloc = tid >> 6, c = tid & 63;
        int col = n0 + c;
        if (col < N)
            fin[(long)(blockIdx.y * 2 + dloc) * H + col] = red[dloc][c] * (1.f / 64.f);
    }
}

// out[d,c]: one warp per output
__global__ void cls_kernel(const float* __restrict__ fin,
                           const float* __restrict__ Wc,
                           const float* __restrict__ bc,
                           float* __restrict__ out)
{
    int gw = blockIdx.x * (blockDim.x >> 5) + (threadIdx.x >> 5);
    int lane = threadIdx.x & 31;
    if (gw >= 128) return;
    int d = gw >> 1, c = gw & 1;
    const float* f = fin + d * H;
    const float* w = Wc + c * H;
    float p = 0.f;
    for (int h = lane; h < H; h += 32) p += f[h] * w[h];
    #pragma unroll
    for (int o = 16; o; o >>= 1) p += __shfl_xor_sync(0xffffffffu, p, o);
    if (lane == 0) out[d * 2 + c] = p + bc[c];
}

// =====================================================================
extern "C" void kernel_launch(void* const* d_in, const int* in_sizes, int n_in,
                              void* d_out, int out_size)
{
    const int*   word_indices = (const int*)  d_in[0];
    const float* E            = (const float*)d_in[1];
    const float* W_sent       = (const float*)d_in[2];
    const float* b_sent       = (const float*)d_in[3];
    const float* W_par        = (const float*)d_in[4];
    const float* b_par        = (const float*)d_in[5];
    const float* W_ch         = (const float*)d_in[6];
    const float* b_ch         = (const float*)d_in[7];
    const float* w_root       = (const float*)d_in[8];
    const float* b_root       = (const float*)d_in[9];
    const float* root_embed   = (const float*)d_in[10];
    const float* W_r          = (const float*)d_in[11];
    const float* b_r          = (const float*)d_in[12];
    const float* W_cls        = (const float*)d_in[13];
    const float* b_cls        = (const float*)d_in[14];

    float* out_ptr = (float*)d_out;
    float* A_ptr   = out_ptr + D * 2;
    float* fri_ptr = A_ptr + D * S * S;

    float *enc, *Pm, *Cm, *Y2, *G, *rs, *fin, *v2;
    cudaGetSymbolAddress((void**)&enc, g_enc);
    cudaGetSymbolAddress((void**)&Pm,  g_P);
    cudaGetSymbolAddress((void**)&Cm,  g_C);
    cudaGetSymbolAddress((void**)&Y2,  g_Y2);
    cudaGetSymbolAddress((void**)&G,   g_G);
    cudaGetSymbolAddress((void**)&rs,  g_rs);
    cudaGetSymbolAddress((void**)&fin, g_fin);
    cudaGetSymbolAddress((void**)&v2,  g_v2);

    cudaFuncSetAttribute(scores_kernel,
                         cudaFuncAttributeMaxDynamicSharedMemorySize, SCORES_SMEM);

    dim3 gEnc((H + BN - 1) / BN, NROWS / BM, 1);
    gemm_tf32_kernel<true><<<gEnc, 256>>>(
        E, word_indices + (L - 1), L,
        W_sent, b_sent, enc,
        nullptr, nullptr, nullptr,
        nullptr, nullptr, nullptr, H, W, W, W, W);

    // P, C (lrelu+bias) and Y2 = enc @ W2^T (linear; W2 rows inside W_r, ld=900)
    dim3 gPCY((H + BN - 1) / BN, NROWS / BM, 3);
    gemm_tf32_kernel<false><<<gPCY, 256>>>(
        enc, nullptr, 0,
        W_par,       b_par,   Pm,
        W_ch,        b_ch,    Cm,
        W_r + 300,   nullptr, Y2,
        H, H, H, H, 900);

    // scores + mask + column softmax -> A (in d_out)
    scores_kernel<<<dim3(4, D), 256, SCORES_SMEM>>>(Pm, Cm, A_ptr);

    // G = A^T @ Y2 per doc; also rs (x==0), fri (x==1), v2 slice (x==2)
    g_kernel<<<dim3(5, D), 256>>>(A_ptr, Y2, enc, w_root, b_root,
                                  W_r, root_embed, G, rs, fri_ptr, v2);

    ri_mean_kernel<<<dim3(5, 32), 256>>>(enc, W_r, b_r, G, rs, fri_ptr, v2, fin);

    cls_kernel<<<8, 512>>>(fin, W_cls, b_cls, out_ptr);
}